// round 3
// baseline (speedup 1.0000x reference)
#include <cuda_runtime.h>
#include <cstdint>
#include <cstddef>

// ---------------- problem constants ----------------
#define NLAYERS 2
#define NB      4
#define BS      256
#define NHID    1024
#define NINP    1024
#define NTOK    32000
#define TT      64
#define BB      64
#define DK      16
#define ROWS    (TT*BB)          // 4096
#define GATES   (NB*4*BS)        // 4096

// output layout: decoded [T,B,NTOK] then h [2,B,NHID] then c [2,B,NHID]
#define H_OFF   ((size_t)ROWS*NTOK)            // 131072000
#define C_OFF   (H_OFF + (size_t)NLAYERS*BB*NHID)

// ---------------- device scratch (no cudaMalloc allowed) ----------------
__device__ float g_x0[(size_t)ROWS*NHID];      // ping
__device__ float g_x1[(size_t)ROWS*NHID];      // pong
__device__ float g_xg[(size_t)ROWS*GATES];     // precomputed x-part of gates (+biases)
__device__ float g_gates[(size_t)BB*GATES];    // per-step gates
__device__ float g_h[BB*NHID];
__device__ float g_c[BB*NHID];

__device__ __forceinline__ float sigmoidf_(float x) { return 1.f / (1.f + expf(-x)); }

// ---------------- embedding gather ----------------
__global__ void embed_kernel(const int* __restrict__ tokens,
                             const float* __restrict__ embW) {
    int row = blockIdx.x;                 // t*B + b
    int tok = tokens[row];
    const float4* src = (const float4*)(embW + (size_t)tok * NINP);
    float4* dst = (float4*)(g_x0 + (size_t)row * NINP);
    dst[threadIdx.x] = src[threadIdx.x];  // 256 thr * float4 = 1024 floats
}

// ---------------- state init / save ----------------
__global__ void init_state_kernel(const float* __restrict__ h0l,
                                  const float* __restrict__ c0l) {
    int i = blockIdx.x * blockDim.x + threadIdx.x;   // 64*256 = 16384 float4
    ((float4*)g_h)[i] = ((const float4*)h0l)[i];
    ((float4*)g_c)[i] = ((const float4*)c0l)[i];
}

__global__ void save_state_kernel(float* __restrict__ outh, float* __restrict__ outc) {
    int i = blockIdx.x * blockDim.x + threadIdx.x;
    ((float4*)outh)[i] = ((const float4*)g_h)[i];
    ((float4*)outc)[i] = ((const float4*)g_c)[i];
}

// ---------------- generic SGEMM: C[M,N] = A[M,K] @ B[N,K]^T + bias1 + bias2 ----------------
// 128x128 tile, BK=8, 256 threads, 8x8 per-thread micro-tile, reg prefetch.
__global__ void __launch_bounds__(256, 2)
gemm128(const float* __restrict__ A, const float* __restrict__ B,
        const float* __restrict__ bias1, const float* __restrict__ bias2,
        float* __restrict__ C, int M, int N, int K) {
    __shared__ float As[8][132];
    __shared__ float Bs[8][132];
    int tid = threadIdx.x;
    int m0 = blockIdx.y * 128, n0 = blockIdx.x * 128;
    int lr = tid >> 1, lk = (tid & 1) << 2;
    const float* Ap = A + (size_t)(m0 + lr) * K + lk;
    const float* Bp = B + (size_t)(n0 + lr) * K + lk;
    float4 av = *(const float4*)Ap;
    float4 bv = *(const float4*)Bp;
    int rowg = (tid >> 4) << 3, colg = (tid & 15) << 3;
    float acc[8][8] = {};
    for (int k0 = 0; k0 < K; k0 += 8) {
        As[lk+0][lr] = av.x; As[lk+1][lr] = av.y; As[lk+2][lr] = av.z; As[lk+3][lr] = av.w;
        Bs[lk+0][lr] = bv.x; Bs[lk+1][lr] = bv.y; Bs[lk+2][lr] = bv.z; Bs[lk+3][lr] = bv.w;
        __syncthreads();
        if (k0 + 8 < K) {
            av = *(const float4*)(Ap + k0 + 8);
            bv = *(const float4*)(Bp + k0 + 8);
        }
        #pragma unroll
        for (int k = 0; k < 8; k++) {
            float a[8], b[8];
            *(float4*)(a)   = *(const float4*)&As[k][rowg];
            *(float4*)(a+4) = *(const float4*)&As[k][rowg+4];
            *(float4*)(b)   = *(const float4*)&Bs[k][colg];
            *(float4*)(b+4) = *(const float4*)&Bs[k][colg+4];
            #pragma unroll
            for (int i = 0; i < 8; i++)
                #pragma unroll
                for (int j = 0; j < 8; j++)
                    acc[i][j] += a[i] * b[j];
        }
        __syncthreads();
    }
    float bcol[8];
    #pragma unroll
    for (int j = 0; j < 8; j++) {
        float v = bias1 ? bias1[n0 + colg + j] : 0.f;
        if (bias2) v += bias2[n0 + colg + j];
        bcol[j] = v;
    }
    #pragma unroll
    for (int i = 0; i < 8; i++) {
        float* Cr = C + (size_t)(m0 + rowg + i) * N + n0 + colg;
        float4 o0 = make_float4(acc[i][0]+bcol[0], acc[i][1]+bcol[1],
                                acc[i][2]+bcol[2], acc[i][3]+bcol[3]);
        float4 o1 = make_float4(acc[i][4]+bcol[4], acc[i][5]+bcol[5],
                                acc[i][6]+bcol[6], acc[i][7]+bcol[7]);
        *(float4*)Cr       = o0;
        *(float4*)(Cr + 4) = o1;
    }
}

// ---------------- recurrent gates: gates[b, n*1024+col] = xg_t + h[b,n,:] @ Whh[n,col,:]^T ----------------
// grid (32, 4): x = 32-col tile within block n, y = n. 256 threads.
// tile: 64 batches x 32 gate-cols, K = 256, chunked KC=64.
__global__ void __launch_bounds__(256, 1)
gates_kernel(const float* __restrict__ xg_t, const float* __restrict__ Whh_l) {
    __shared__ float Hs[64][64];     // [b][k-chunk]
    __shared__ float Wt[64][34];     // [k-chunk][row], padded
    int n = blockIdx.y, jt = blockIdx.x, tid = threadIdx.x;
    int colg = tid & 15;             // 2 cols each
    int bq   = tid >> 4;             // 4 batches each
    int col0 = n * 1024 + jt * 32 + colg * 2;

    float acc[4][2];
    #pragma unroll
    for (int i = 0; i < 4; i++) {
        const float* xr = xg_t + (size_t)(bq*4 + i) * GATES + col0;
        acc[i][0] = xr[0]; acc[i][1] = xr[1];
    }

    const float* Wb = Whh_l + (size_t)(n * 1024 + jt * 32) * 256;

    for (int kc = 0; kc < 256; kc += 64) {
        for (int i = tid; i < 64*16; i += 256) {
            int b = i >> 4, k4 = (i & 15) << 2;
            *(float4*)&Hs[b][k4] = *(const float4*)&g_h[b*NHID + n*BS + kc + k4];
        }
        for (int i = tid; i < 32*16; i += 256) {
            int r = i >> 4, k4 = (i & 15) << 2;
            float4 w = *(const float4*)&Wb[(size_t)r*256 + kc + k4];
            Wt[k4+0][r] = w.x; Wt[k4+1][r] = w.y; Wt[k4+2][r] = w.z; Wt[k4+3][r] = w.w;
        }
        __syncthreads();
        #pragma unroll
        for (int k = 0; k < 64; k += 4) {
            float2 w0 = *(const float2*)&Wt[k+0][colg*2];
            float2 w1 = *(const float2*)&Wt[k+1][colg*2];
            float2 w2 = *(const float2*)&Wt[k+2][colg*2];
            float2 w3 = *(const float2*)&Wt[k+3][colg*2];
            #pragma unroll
            for (int i = 0; i < 4; i++) {
                float4 h = *(const float4*)&Hs[bq*4 + i][k];
                acc[i][0] += h.x*w0.x; acc[i][1] += h.x*w0.y;
                acc[i][0] += h.y*w1.x; acc[i][1] += h.y*w1.y;
                acc[i][0] += h.z*w2.x; acc[i][1] += h.z*w2.y;
                acc[i][0] += h.w*w3.x; acc[i][1] += h.w*w3.y;
            }
        }
        __syncthreads();
    }
    #pragma unroll
    for (int i = 0; i < 4; i++) {
        float* gr = g_gates + (size_t)(bq*4 + i) * GATES + col0;
        gr[0] = acc[i][0]; gr[1] = acc[i][1];
    }
}

// ---------------- fused LSTM cell + MHA + residual + LayerNorm ----------------
// one CTA (256 threads) per batch element.
__global__ void __launch_bounds__(256, 4)
cell_mha_kernel(const float* __restrict__ wq, const float* __restrict__ bq,
                const float* __restrict__ wk, const float* __restrict__ bk,
                const float* __restrict__ wv, const float* __restrict__ bv,
                const float* __restrict__ wfc, const float* __restrict__ bfc,
                const float* __restrict__ lng, const float* __restrict__ lnb,
                float* __restrict__ x_next, int t) {
    __shared__ float hl[NB][BS];
    __shared__ float sq[NB][DK], sk[NB][DK], sv[NB][DK];
    __shared__ float attnw[NB][NB];
    __shared__ float outv[NB][DK];
    __shared__ float part[NB][2][8];
    __shared__ float mu_s[NB], rstd_s[NB];

    int b = blockIdx.x, tid = threadIdx.x;
    int warp = tid >> 5, lane = tid & 31;

    // ---- LSTM cell (torch gate order i,f,g,o) ----
    for (int e = tid; e < NB*BS; e += 256) {
        int n = e >> 8, j = e & 255;
        const float* gr = g_gates + (size_t)b * GATES + n * 1024 + j;
        float ig = gr[0], fg = gr[256], gg = gr[512], og = gr[768];
        int ci = b * NHID + n * BS + j;
        float cn = sigmoidf_(fg) * g_c[ci] + sigmoidf_(ig) * tanhf(gg);
        g_c[ci] = cn;
        hl[n][j] = sigmoidf_(og) * tanhf(cn);
    }
    __syncthreads();

    // ---- q,k,v projections: 3 mats * 4 blocks * 16 dims = 192 dots of len 256 ----
    for (int idx = warp; idx < 3*NB*DK; idx += 8) {
        int mat = idx >> 6, n = (idx >> 4) & 3, d = idx & 15;
        const float* W = (mat == 0 ? wq : mat == 1 ? wk : wv) + d * BS;
        float s = 0.f;
        #pragma unroll
        for (int j = lane; j < BS; j += 32) s += hl[n][j] * W[j];
        #pragma unroll
        for (int o = 16; o; o >>= 1) s += __shfl_xor_sync(0xffffffffu, s, o);
        if (lane == 0) {
            float bias = (mat == 0 ? bq[d] : mat == 1 ? bk[d] : bv[d]);
            (mat == 0 ? sq : mat == 1 ? sk : sv)[n][d] = s + bias;
        }
    }
    __syncthreads();

    // ---- 4x4 attention + softmax (16 lanes of warp 0) ----
    if (tid < 16) {
        int n = tid >> 2, m = tid & 3;
        float l = 0.f;
        #pragma unroll
        for (int d = 0; d < DK; d++) l += sq[n][d] * sk[m][d];
        l *= 0.25f;   // 1/sqrt(16)
        float mx = l;
        mx = fmaxf(mx, __shfl_xor_sync(0xffffu, mx, 1));
        mx = fmaxf(mx, __shfl_xor_sync(0xffffu, mx, 2));
        float e = expf(l - mx);
        float s = e;
        s += __shfl_xor_sync(0xffffu, s, 1);
        s += __shfl_xor_sync(0xffffu, s, 2);
        attnw[n][m] = e / s;
    }
    __syncthreads();

    // ---- out = attn @ v ----
    if (tid < 64) {
        int n = tid >> 4, d = tid & 15;
        float s = 0.f;
        #pragma unroll
        for (int m = 0; m < NB; m++) s += attnw[n][m] * sv[m][d];
        outv[n][d] = s;
    }
    __syncthreads();

    // ---- fc proj + residual; thread owns column j = tid for all 4 blocks ----
    int j = tid;
    float wfr[DK];
    {
        const float4* wf4 = (const float4*)(wfc + (size_t)j * DK);
        *(float4*)(wfr)    = wf4[0];
        *(float4*)(wfr+4)  = wf4[1];
        *(float4*)(wfr+8)  = wf4[2];
        *(float4*)(wfr+12) = wf4[3];
    }
    float bfj = bfc[j], lgj = lng[j], lbj = lnb[j];
    float r[NB];
    #pragma unroll
    for (int n = 0; n < NB; n++) {
        float s = bfj;
        #pragma unroll
        for (int d = 0; d < DK; d++) s += outv[n][d] * wfr[d];
        r[n] = s + hl[n][j];
    }

    // ---- LayerNorm per (b,n): reduce over 256 cols ----
    #pragma unroll
    for (int n = 0; n < NB; n++) {
        float s1 = r[n], s2 = r[n] * r[n];
        #pragma unroll
        for (int o = 16; o; o >>= 1) {
            s1 += __shfl_xor_sync(0xffffffffu, s1, o);
            s2 += __shfl_xor_sync(0xffffffffu, s2, o);
        }
        if (lane == 0) { part[n][0][warp] = s1; part[n][1][warp] = s2; }
    }
    __syncthreads();
    if (tid < 4) {
        float S1 = 0.f, S2 = 0.f;
        #pragma unroll
        for (int w = 0; w < 8; w++) { S1 += part[tid][0][w]; S2 += part[tid][1][w]; }
        float mu = S1 * (1.f / 256.f);
        mu_s[tid] = mu;
        rstd_s[tid] = rsqrtf(S2 * (1.f / 256.f) - mu * mu + 1e-5f);
    }
    __syncthreads();
    #pragma unroll
    for (int n = 0; n < NB; n++) {
        float hn = (r[n] - mu_s[n]) * rstd_s[n] * lgj + lbj;
        g_h[b * NHID + n * BS + j] = hn;
        x_next[(size_t)(t * BB + b) * NHID + n * BS + j] = hn;
    }
}

// ---------------- host orchestration ----------------
extern "C" void kernel_launch(void* const* d_in, const int* in_sizes, int n_in,
                              void* d_out, int out_size) {
    const int*   tokens = (const int*)  d_in[0];
    const float* h0     = (const float*)d_in[1];
    const float* c0     = (const float*)d_in[2];
    const float* embW   = (const float*)d_in[3];
    const float* Wih    = (const float*)d_in[4];
    const float* Whh    = (const float*)d_in[5];
    const float* bih    = (const float*)d_in[6];
    const float* bhh    = (const float*)d_in[7];
    const float* wq     = (const float*)d_in[8];
    const float* bq     = (const float*)d_in[9];
    const float* wk     = (const float*)d_in[10];
    const float* bk     = (const float*)d_in[11];
    const float* wv     = (const float*)d_in[12];
    const float* bv     = (const float*)d_in[13];
    const float* wfc    = (const float*)d_in[14];
    const float* bfc    = (const float*)d_in[15];
    const float* lng    = (const float*)d_in[16];
    const float* lnb    = (const float*)d_in[17];
    const float* decW   = (const float*)d_in[18];
    const float* decb   = (const float*)d_in[19];
    float* out = (float*)d_out;

    float *x0, *x1, *xg;
    cudaGetSymbolAddress((void**)&x0, g_x0);
    cudaGetSymbolAddress((void**)&x1, g_x1);
    cudaGetSymbolAddress((void**)&xg, g_xg);

    embed_kernel<<<ROWS, 256>>>(tokens, embW);

    float* xcur = x0;
    float* xnext = x1;
    for (int l = 0; l < NLAYERS; l++) {
        init_state_kernel<<<64, 256>>>(h0 + (size_t)l * BB * NHID,
                                       c0 + (size_t)l * BB * NHID);
        // xg = xcur @ W_ih[l]^T + (b_ih[l] + b_hh[l])
        gemm128<<<dim3(GATES/128, ROWS/128), 256>>>(
            xcur, Wih + (size_t)l * GATES * NINP,
            bih + (size_t)l * GATES, bhh + (size_t)l * GATES,
            xg, ROWS, GATES, NINP);
        for (int t = 0; t < TT; t++) {
            gates_kernel<<<dim3(32, NB), 256>>>(
                xg + (size_t)t * BB * GATES,
                Whh + (size_t)l * NB * 1024 * 256);
            cell_mha_kernel<<<BB, 256>>>(wq, bq, wk, bk, wv, bv, wfc, bfc,
                                         lng, lnb, xnext, t);
        }
        save_state_kernel<<<64, 256>>>(out + H_OFF + (size_t)l * BB * NHID,
                                       out + C_OFF + (size_t)l * BB * NHID);
        float* tmp = xcur; xcur = xnext; xnext = tmp;
    }

    // decode: out = x @ dec_W^T + dec_b
    gemm128<<<dim3(NTOK/128, ROWS/128), 256>>>(
        xcur, decW, decb, nullptr, out, ROWS, NTOK, NINP);
}

// round 6
// speedup vs baseline: 1.0089x; 1.0089x over previous
#include <cuda_runtime.h>
#include <cstdint>
#include <cstddef>

// ---------------- problem constants ----------------
#define NLAYERS 2
#define NB      4
#define BS      256
#define NHID    1024
#define NINP    1024
#define NTOK    32000
#define TT      64
#define BB      64
#define DK      16
#define ROWS    (TT*BB)          // 4096
#define GATES   (NB*4*BS)        // 4096

// output layout: decoded [T,B,NTOK] then h [2,B,NHID] then c [2,B,NHID]
#define H_OFF   ((size_t)ROWS*NTOK)
#define C_OFF   (H_OFF + (size_t)NLAYERS*BB*NHID)

// ---------------- device scratch ----------------
__device__ float g_x0[(size_t)ROWS*NHID];
__device__ float g_x1[(size_t)ROWS*NHID];
__device__ float g_xg[(size_t)ROWS*GATES];
__device__ float g_gates[(size_t)BB*GATES];
__device__ float g_h[BB*NHID];
__device__ float g_c[BB*NHID];
__device__ unsigned g_bar_counter;

__device__ __forceinline__ float sigmoidf_(float x) { return 1.f / (1.f + expf(-x)); }

typedef unsigned long long ull;

// packed fp32x2 FMA (Blackwell): d = a*b + d on both lanes
__device__ __forceinline__ void ffma2(ull &d, ull a, ull b) {
    asm("fma.rn.f32x2 %0, %1, %2, %3;" : "=l"(d) : "l"(a), "l"(b), "l"(d));
}
__device__ __forceinline__ ull dup2(float x) {
    ull r; unsigned u = __float_as_uint(x);
    asm("mov.b64 %0, {%1, %1};" : "=l"(r) : "r"(u));
    return r;
}
__device__ __forceinline__ float2 u2f2(ull v) {
    float2 f; unsigned lo, hi;
    asm("mov.b64 {%0, %1}, %2;" : "=r"(lo), "=r"(hi) : "l"(v));
    f.x = __uint_as_float(lo); f.y = __uint_as_float(hi);
    return f;
}

// ---------------- embedding gather ----------------
__global__ void embed_kernel(const int* __restrict__ tokens,
                             const float* __restrict__ embW) {
    int row = blockIdx.x;
    int tok = tokens[row];
    const float4* src = (const float4*)(embW + (size_t)tok * NINP);
    float4* dst = (float4*)(g_x0 + (size_t)row * NINP);
    dst[threadIdx.x] = src[threadIdx.x];
}

// ---------------- state init / save ----------------
__global__ void init_state_kernel(const float* __restrict__ h0l,
                                  const float* __restrict__ c0l) {
    int i = blockIdx.x * blockDim.x + threadIdx.x;
    ((float4*)g_h)[i] = ((const float4*)h0l)[i];
    ((float4*)g_c)[i] = ((const float4*)c0l)[i];
    if (i == 0) g_bar_counter = 0;
}

__global__ void save_state_kernel(float* __restrict__ outh, float* __restrict__ outc) {
    int i = blockIdx.x * blockDim.x + threadIdx.x;
    ((float4*)outh)[i] = ((const float4*)g_h)[i];
    ((float4*)outc)[i] = ((const float4*)g_c)[i];
}

// ---------------- SGEMM (FFMA2): C[M,N] = A[M,K] @ B[N,K]^T + bias1 + bias2 ----------------
__global__ void __launch_bounds__(256, 2)
gemm128(const float* __restrict__ A, const float* __restrict__ B,
        const float* __restrict__ bias1, const float* __restrict__ bias2,
        float* __restrict__ C, int M, int N, int K) {
    __shared__ float As[8][132];
    __shared__ float Bs[8][132];
    int tid = threadIdx.x;
    int m0 = blockIdx.y * 128, n0 = blockIdx.x * 128;
    int lr = tid >> 1, lk = (tid & 1) << 2;
    const float* Ap = A + (size_t)(m0 + lr) * K + lk;
    const float* Bp = B + (size_t)(n0 + lr) * K + lk;
    float4 av = *(const float4*)Ap;
    float4 bv = *(const float4*)Bp;
    int rowg = (tid >> 4) << 3, colg = (tid & 15) << 3;
    ull acc2[8][4];
    #pragma unroll
    for (int i = 0; i < 8; i++)
        #pragma unroll
        for (int j = 0; j < 4; j++) acc2[i][j] = 0ull;

    for (int k0 = 0; k0 < K; k0 += 8) {
        As[lk+0][lr] = av.x; As[lk+1][lr] = av.y; As[lk+2][lr] = av.z; As[lk+3][lr] = av.w;
        Bs[lk+0][lr] = bv.x; Bs[lk+1][lr] = bv.y; Bs[lk+2][lr] = bv.z; Bs[lk+3][lr] = bv.w;
        __syncthreads();
        if (k0 + 8 < K) {
            av = *(const float4*)(Ap + k0 + 8);
            bv = *(const float4*)(Bp + k0 + 8);
        }
        #pragma unroll
        for (int k = 0; k < 8; k++) {
            float a[8];
            *(float4*)(a)   = *(const float4*)&As[k][rowg];
            *(float4*)(a+4) = *(const float4*)&As[k][rowg+4];
            ulonglong2 bb0 = *(const ulonglong2*)&Bs[k][colg];
            ulonglong2 bb1 = *(const ulonglong2*)&Bs[k][colg+4];
            #pragma unroll
            for (int i = 0; i < 8; i++) {
                ull aa = dup2(a[i]);
                ffma2(acc2[i][0], aa, bb0.x);
                ffma2(acc2[i][1], aa, bb0.y);
                ffma2(acc2[i][2], aa, bb1.x);
                ffma2(acc2[i][3], aa, bb1.y);
            }
        }
        __syncthreads();
    }
    float bcol[8];
    #pragma unroll
    for (int j = 0; j < 8; j++) {
        float v = bias1 ? bias1[n0 + colg + j] : 0.f;
        if (bias2) v += bias2[n0 + colg + j];
        bcol[j] = v;
    }
    #pragma unroll
    for (int i = 0; i < 8; i++) {
        float* Cr = C + (size_t)(m0 + rowg + i) * N + n0 + colg;
        float2 p0 = u2f2(acc2[i][0]), p1 = u2f2(acc2[i][1]);
        float2 p2 = u2f2(acc2[i][2]), p3 = u2f2(acc2[i][3]);
        float4 o0 = make_float4(p0.x+bcol[0], p0.y+bcol[1], p1.x+bcol[2], p1.y+bcol[3]);
        float4 o1 = make_float4(p2.x+bcol[4], p2.y+bcol[5], p3.x+bcol[6], p3.y+bcol[7]);
        *(float4*)Cr       = o0;
        *(float4*)(Cr + 4) = o1;
    }
}

// ---------------- software grid barrier (all 128 CTAs resident) ----------------
#define GRID_CTAS 128
__device__ __forceinline__ void grid_bar(unsigned &target) {
    __syncthreads();
    if (threadIdx.x == 0) {
        target += GRID_CTAS;
        __threadfence();
        atomicAdd(&g_bar_counter, 1u);
        while (*(volatile unsigned*)&g_bar_counter < target) { }
    }
    __syncthreads();
}

// ---------------- persistent layer kernel: 64 time steps fused ----------------
// 128 CTAs x 256 threads. CTA k: gate tile n=k>>5, jt=k&31 (cols n*1024+jt*32..+32).
// Whh slice (32x256) lives in smem for the whole layer.
// Phase A: gates = xg[t] + h @ Whh^T  -> g_gates  (all CTAs)
// Phase B: LSTM cell + MHA + LN for batch b = blockIdx.x  (CTAs 0..63)
#define HS_PAD 36
__global__ void __launch_bounds__(256, 1)
layer_kernel(const float* __restrict__ xg, const float* __restrict__ Whh_l,
             const float* __restrict__ wq, const float* __restrict__ bq,
             const float* __restrict__ wk, const float* __restrict__ bk,
             const float* __restrict__ wv, const float* __restrict__ bv,
             const float* __restrict__ wfc, const float* __restrict__ bfc,
             const float* __restrict__ lng, const float* __restrict__ lnb,
             float* __restrict__ x_next) {
    extern __shared__ float dyn[];
    float* Wt = dyn;                    // [256][32]  k-major weight slice
    float* Hs = dyn + 256*32;           // [64][HS_PAD] h chunk (32 k's)

    __shared__ float hl[NB][BS];
    __shared__ float sq[NB][DK], sk[NB][DK], sv[NB][DK];
    __shared__ float attnw[NB][NB];
    __shared__ float outv[NB][DK];
    __shared__ float part[NB][2][8];
    __shared__ float mu_s[NB], rstd_s[NB];

    int cta = blockIdx.x;
    int n = cta >> 5, jt = cta & 31;
    int tid = threadIdx.x;
    int warp = tid >> 5, lane = tid & 31;

    // ---- load Whh slice into smem once (transposed to [k][j]) ----
    for (int e = tid; e < 32*64; e += 256) {
        int j = e >> 6;             // 0..31
        int k4 = (e & 63) << 2;     // 0..252
        float4 w = *(const float4*)&Whh_l[(size_t)(n*1024 + jt*32 + j)*256 + k4];
        Wt[(k4+0)*32 + j] = w.x;
        Wt[(k4+1)*32 + j] = w.y;
        Wt[(k4+2)*32 + j] = w.z;
        Wt[(k4+3)*32 + j] = w.w;
    }
    __syncthreads();

    int colg = tid & 15;            // col pair index
    int bq4  = tid >> 4;            // batch quad index
    int col0 = n * 1024 + jt * 32 + colg * 2;

    unsigned bar_target = 0;

    for (int t = 0; t < TT; t++) {
        // ================= phase A: gates =================
        ull acc2[4];
        #pragma unroll
        for (int i = 0; i < 4; i++) {
            float2 x = __ldcg((const float2*)&xg[(size_t)(t*BB + bq4*4 + i) * GATES + col0]);
            acc2[i] = *(ull*)&x;
        }
        for (int kc = 0; kc < 256; kc += 32) {
            #pragma unroll
            for (int u = 0; u < 2; u++) {
                int e = tid + u * 256;
                int b = e >> 3, k4 = (e & 7) << 2;
                float4 h = __ldcg((const float4*)&g_h[b*NHID + n*BS + kc + k4]);
                *(float4*)&Hs[b*HS_PAD + k4] = h;
            }
            __syncthreads();
            #pragma unroll
            for (int k = 0; k < 32; k += 4) {
                ull w0 = *(const ull*)&Wt[(kc+k+0)*32 + colg*2];
                ull w1 = *(const ull*)&Wt[(kc+k+1)*32 + colg*2];
                ull w2 = *(const ull*)&Wt[(kc+k+2)*32 + colg*2];
                ull w3 = *(const ull*)&Wt[(kc+k+3)*32 + colg*2];
                #pragma unroll
                for (int i = 0; i < 4; i++) {
                    float4 h = *(const float4*)&Hs[(bq4*4 + i)*HS_PAD + k];
                    ffma2(acc2[i], dup2(h.x), w0);
                    ffma2(acc2[i], dup2(h.y), w1);
                    ffma2(acc2[i], dup2(h.z), w2);
                    ffma2(acc2[i], dup2(h.w), w3);
                }
            }
            __syncthreads();
        }
        #pragma unroll
        for (int i = 0; i < 4; i++) {
            float2 v = u2f2(acc2[i]);
            __stcg((float2*)&g_gates[(size_t)(bq4*4 + i) * GATES + col0], v);
        }

        grid_bar(bar_target);   // gates visible

        // ================= phase B: cell + MHA + LN =================
        if (cta < BB) {
            int b = cta;
            // LSTM cell (i,f,g,o)
            for (int e = tid; e < NB*BS; e += 256) {
                int nn = e >> 8, j = e & 255;
                const float* gr = g_gates + (size_t)b * GATES + nn * 1024 + j;
                float ig = __ldcg(gr +   0);
                float fg = __ldcg(gr + 256);
                float gg = __ldcg(gr + 512);
                float og = __ldcg(gr + 768);
                int ci = b * NHID + nn * BS + j;
                float cn = sigmoidf_(fg) * __ldcg(&g_c[ci]) + sigmoidf_(ig) * tanhf(gg);
                __stcg(&g_c[ci], cn);
                hl[nn][j] = sigmoidf_(og) * tanhf(cn);
            }
            __syncthreads();

            // q,k,v projections
            for (int idx = warp; idx < 3*NB*DK; idx += 8) {
                int mat = idx >> 6, nn = (idx >> 4) & 3, d = idx & 15;
                const float* W = (mat == 0 ? wq : mat == 1 ? wk : wv) + d * BS;
                float s = 0.f;
                #pragma unroll
                for (int j = lane; j < BS; j += 32) s += hl[nn][j] * W[j];
                #pragma unroll
                for (int o = 16; o; o >>= 1) s += __shfl_xor_sync(0xffffffffu, s, o);
                if (lane == 0) {
                    float bias = (mat == 0 ? bq[d] : mat == 1 ? bk[d] : bv[d]);
                    (mat == 0 ? sq : mat == 1 ? sk : sv)[nn][d] = s + bias;
                }
            }
            __syncthreads();

            // 4x4 attention + softmax
            if (tid < 16) {
                int nn = tid >> 2, m = tid & 3;
                float l = 0.f;
                #pragma unroll
                for (int d = 0; d < DK; d++) l += sq[nn][d] * sk[m][d];
                l *= 0.25f;
                float mx = l;
                mx = fmaxf(mx, __shfl_xor_sync(0xffffu, mx, 1));
                mx = fmaxf(mx, __shfl_xor_sync(0xffffu, mx, 2));
                float e = expf(l - mx);
                float s = e;
                s += __shfl_xor_sync(0xffffu, s, 1);
                s += __shfl_xor_sync(0xffffu, s, 2);
                attnw[nn][m] = e / s;
            }
            __syncthreads();

            if (tid < 64) {
                int nn = tid >> 4, d = tid & 15;
                float s = 0.f;
                #pragma unroll
                for (int m = 0; m < NB; m++) s += attnw[nn][m] * sv[m][d];
                outv[nn][d] = s;
            }
            __syncthreads();

            // fc + residual + LayerNorm; thread owns column j
            int j = tid;
            float wfr[DK];
            {
                const float4* wf4 = (const float4*)(wfc + (size_t)j * DK);
                *(float4*)(wfr)    = wf4[0];
                *(float4*)(wfr+4)  = wf4[1];
                *(float4*)(wfr+8)  = wf4[2];
                *(float4*)(wfr+12) = wf4[3];
            }
            float bfj = bfc[j], lgj = lng[j], lbj = lnb[j];
            float r[NB];
            #pragma unroll
            for (int nn = 0; nn < NB; nn++) {
                float s = bfj;
                #pragma unroll
                for (int d = 0; d < DK; d++) s += outv[nn][d] * wfr[d];
                r[nn] = s + hl[nn][j];
            }
            #pragma unroll
            for (int nn = 0; nn < NB; nn++) {
                float s1 = r[nn], s2 = r[nn] * r[nn];
                #pragma unroll
                for (int o = 16; o; o >>= 1) {
                    s1 += __shfl_xor_sync(0xffffffffu, s1, o);
                    s2 += __shfl_xor_sync(0xffffffffu, s2, o);
                }
                if (lane == 0) { part[nn][0][warp] = s1; part[nn][1][warp] = s2; }
            }
            __syncthreads();
            if (tid < 4) {
                float S1 = 0.f, S2 = 0.f;
                #pragma unroll
                for (int w = 0; w < 8; w++) { S1 += part[tid][0][w]; S2 += part[tid][1][w]; }
                float mu = S1 * (1.f / 256.f);
                mu_s[tid] = mu;
                rstd_s[tid] = rsqrtf(S2 * (1.f / 256.f) - mu * mu + 1e-5f);
            }
            __syncthreads();
            #pragma unroll
            for (int nn = 0; nn < NB; nn++) {
                float hn = (r[nn] - mu_s[nn]) * rstd_s[nn] * lgj + lbj;
                __stcg(&g_h[b * NHID + nn * BS + j], hn);
                x_next[(size_t)(t * BB + b) * NHID + nn * BS + j] = hn;
            }
        }

        grid_bar(bar_target);   // h visible for next step
    }
}

// ---------------- host orchestration ----------------
extern "C" void kernel_launch(void* const* d_in, const int* in_sizes, int n_in,
                              void* d_out, int out_size) {
    const int*   tokens = (const int*)  d_in[0];
    const float* h0     = (const float*)d_in[1];
    const float* c0     = (const float*)d_in[2];
    const float* embW   = (const float*)d_in[3];
    const float* Wih    = (const float*)d_in[4];
    const float* Whh    = (const float*)d_in[5];
    const float* bih    = (const float*)d_in[6];
    const float* bhh    = (const float*)d_in[7];
    const float* wq     = (const float*)d_in[8];
    const float* bq     = (const float*)d_in[9];
    const float* wk     = (const float*)d_in[10];
    const float* bk     = (const float*)d_in[11];
    const float* wv     = (const float*)d_in[12];
    const float* bv     = (const float*)d_in[13];
    const float* wfc    = (const float*)d_in[14];
    const float* bfc    = (const float*)d_in[15];
    const float* lng    = (const float*)d_in[16];
    const float* lnb    = (const float*)d_in[17];
    const float* decW   = (const float*)d_in[18];
    const float* decb   = (const float*)d_in[19];
    float* out = (float*)d_out;

    float *x0, *x1, *xg;
    cudaGetSymbolAddress((void**)&x0, g_x0);
    cudaGetSymbolAddress((void**)&x1, g_x1);
    cudaGetSymbolAddress((void**)&xg, g_xg);

    const int dyn_smem = (256*32 + 64*HS_PAD) * sizeof(float);   // 41984 B

    embed_kernel<<<ROWS, 256>>>(tokens, embW);

    float* xcur = x0;
    float* xnext = x1;
    for (int l = 0; l < NLAYERS; l++) {
        init_state_kernel<<<64, 256>>>(h0 + (size_t)l * BB * NHID,
                                       c0 + (size_t)l * BB * NHID);
        gemm128<<<dim3(GATES/128, ROWS/128), 256>>>(
            xcur, Wih + (size_t)l * GATES * NINP,
            bih + (size_t)l * GATES, bhh + (size_t)l * GATES,
            xg, ROWS, GATES, NINP);
        layer_kernel<<<GRID_CTAS, 256, dyn_smem>>>(
            xg, Whh + (size_t)l * NB * 1024 * 256,
            wq, bq, wk, bk, wv, bv, wfc, bfc, lng, lnb, xnext);
        save_state_kernel<<<64, 256>>>(out + H_OFF + (size_t)l * BB * NHID,
                                       out + C_OFF + (size_t)l * BB * NHID);
        float* tmp = xcur; xcur = xnext; xnext = tmp;
    }

    gemm128<<<dim3(NTOK/128, ROWS/128), 256>>>(
        xcur, decW, decb, nullptr, out, ROWS, NTOK, NINP);
}

// round 8
// speedup vs baseline: 1.3725x; 1.3603x over previous
#include <cuda_runtime.h>
#include <cstdint>
#include <cstddef>

// ---------------- problem constants ----------------
#define NLAYERS 2
#define NB      4
#define BS      256
#define NHID    1024
#define NINP    1024
#define NTOK    32000
#define TT      64
#define BB      64
#define DK      16
#define ROWS    (TT*BB)          // 4096
#define GATES   (NB*4*BS)        // 4096

#define H_OFF   ((size_t)ROWS*NTOK)
#define C_OFF   (H_OFF + (size_t)NLAYERS*BB*NHID)

// ---------------- device scratch ----------------
__device__ float g_x0[(size_t)ROWS*NHID];
__device__ float g_x1[(size_t)ROWS*NHID];
__device__ float g_xg[(size_t)ROWS*GATES];
__device__ float g_gates[(size_t)BB*GATES];
__device__ float g_h[BB*NHID];
__device__ float g_c[BB*NHID];
__device__ unsigned g_bar_counter;
// tf32 copies
__device__ float g_decW_t[(size_t)NTOK*NHID];            // 131 MB (tf32-rounded)
__device__ float g_Wih_hi[(size_t)NLAYERS*GATES*NINP];   // 33.5 MB
__device__ float g_Wih_lo[(size_t)NLAYERS*GATES*NINP];   // 33.5 MB
__device__ float g_x_hi[(size_t)ROWS*NHID];              // 16.8 MB
__device__ float g_x_lo[(size_t)ROWS*NHID];              // 16.8 MB

__device__ __forceinline__ float sigmoidf_(float x) { return 1.f / (1.f + expf(-x)); }

typedef unsigned long long ull;

__device__ __forceinline__ void ffma2(ull &d, ull a, ull b) {
    asm("fma.rn.f32x2 %0, %1, %2, %3;" : "=l"(d) : "l"(a), "l"(b), "l"(d));
}
__device__ __forceinline__ ull dup2(float x) {
    ull r; unsigned u = __float_as_uint(x);
    asm("mov.b64 %0, {%1, %1};" : "=l"(r) : "r"(u));
    return r;
}
__device__ __forceinline__ float2 u2f2(ull v) {
    float2 f; unsigned lo, hi;
    asm("mov.b64 {%0, %1}, %2;" : "=r"(lo), "=r"(hi) : "l"(v));
    f.x = __uint_as_float(lo); f.y = __uint_as_float(hi);
    return f;
}

__device__ __forceinline__ float f2tf_f(float f) {
    uint32_t r; asm("cvt.rna.tf32.f32 %0, %1;" : "=r"(r) : "f"(f));
    return __uint_as_float(r);
}
__device__ __forceinline__ void cp16(uint32_t saddr, const void* g) {
    asm volatile("cp.async.cg.shared.global [%0], [%1], 16;" :: "r"(saddr), "l"(g));
}
__device__ __forceinline__ void cp_commit() { asm volatile("cp.async.commit_group;"); }
__device__ __forceinline__ void cp_wait1()  { asm volatile("cp.async.wait_group 1;"); }
__device__ __forceinline__ void cp_wait0()  { asm volatile("cp.async.wait_group 0;"); }

__device__ __forceinline__ void mma_tf32(float c[4],
                                         uint32_t a0, uint32_t a1, uint32_t a2, uint32_t a3,
                                         uint32_t b0, uint32_t b1) {
    asm("mma.sync.aligned.m16n8k8.row.col.f32.tf32.tf32.f32 "
        "{%0,%1,%2,%3}, {%4,%5,%6,%7}, {%8,%9}, {%0,%1,%2,%3};"
        : "+f"(c[0]), "+f"(c[1]), "+f"(c[2]), "+f"(c[3])
        : "r"(a0), "r"(a1), "r"(a2), "r"(a3), "r"(b0), "r"(b1));
}

// ---------------- tf32 conversion: out = round_tf32(in) ----------------
__global__ void cvt_tf32_kernel(const float* __restrict__ in, float* __restrict__ out) {
    size_t i = ((size_t)blockIdx.x * 256 + threadIdx.x) * 4;
    float4 v = *(const float4*)(in + i);
    float4 o;
    o.x = f2tf_f(v.x); o.y = f2tf_f(v.y); o.z = f2tf_f(v.z); o.w = f2tf_f(v.w);
    *(float4*)(out + i) = o;
}

// ---------------- tf32 split: hi = round_tf32(in), lo = round_tf32(in - hi) ----------------
__global__ void split_tf32_kernel(const float* __restrict__ in,
                                  float* __restrict__ hi, float* __restrict__ lo) {
    size_t i = ((size_t)blockIdx.x * 256 + threadIdx.x) * 4;
    float4 v = *(const float4*)(in + i);
    float4 h, l;
    h.x = f2tf_f(v.x); l.x = f2tf_f(v.x - h.x);
    h.y = f2tf_f(v.y); l.y = f2tf_f(v.y - h.y);
    h.z = f2tf_f(v.z); l.z = f2tf_f(v.z - h.z);
    h.w = f2tf_f(v.w); l.w = f2tf_f(v.w - h.w);
    *(float4*)(hi + i) = h;
    *(float4*)(lo + i) = l;
}

// ---------------- embedding gather ----------------
__global__ void embed_kernel(const int* __restrict__ tokens,
                             const float* __restrict__ embW) {
    int row = blockIdx.x;
    int tok = tokens[row];
    const float4* src = (const float4*)(embW + (size_t)tok * NINP);
    float4* dst = (float4*)(g_x0 + (size_t)row * NINP);
    dst[threadIdx.x] = src[threadIdx.x];
}

// ---------------- state init / save ----------------
__global__ void init_state_kernel(const float* __restrict__ h0l,
                                  const float* __restrict__ c0l) {
    int i = blockIdx.x * blockDim.x + threadIdx.x;
    ((float4*)g_h)[i] = ((const float4*)h0l)[i];
    ((float4*)g_c)[i] = ((const float4*)c0l)[i];
    if (i == 0) g_bar_counter = 0;
}

__global__ void save_state_kernel(float* __restrict__ outh, float* __restrict__ outc) {
    int i = blockIdx.x * blockDim.x + threadIdx.x;
    ((float4*)outh)[i] = ((const float4*)g_h)[i];
    ((float4*)outc)[i] = ((const float4*)g_c)[i];
}

// ---------------- tf32 tensor-core GEMM with multi-pass accumulation ----------------
// C[M,N] = sum_p A_p[M,K] @ B_p[N,K]^T + bias1 + bias2   (npass = 1 or 3)
// 128x128 tile, BK=32, cp.async double buffer, 8 warps (wm=warp&1 64 rows, wn=warp>>1 32 cols).
#define TFK 32
#define LDT 36
#define TILE_F (128*LDT)
__global__ void __launch_bounds__(256, 2)
gemm_tf32(const float* __restrict__ A0, const float* __restrict__ A1, const float* __restrict__ A2,
          const float* __restrict__ B0, const float* __restrict__ B1, const float* __restrict__ B2,
          int npass,
          const float* __restrict__ bias1, const float* __restrict__ bias2,
          float* __restrict__ C, int M, int N, int K) {
    extern __shared__ float sm[];
    float* Abuf[2] = { sm,            sm + TILE_F };
    float* Bbuf[2] = { sm + 2*TILE_F, sm + 3*TILE_F };

    int tid  = threadIdx.x;
    int m0 = blockIdx.y * 128, n0 = blockIdx.x * 128;
    int warp = tid >> 5, lane = tid & 31;
    int wm = warp & 1, wn = warp >> 1;
    int g = lane >> 2, c = lane & 3;

    int lrow = tid >> 1, lcol = (tid & 1) * 16;
    size_t aoff = (size_t)(m0 + lrow) * K + lcol;
    size_t boff = (size_t)(n0 + lrow) * K + lcol;
    const float* Ab[3] = { A0 + aoff, A1 + aoff, A2 + aoff };
    const float* Bb[3] = { B0 + boff, B1 + boff, B2 + boff };

    uint32_t sA[2], sB[2];
    #pragma unroll
    for (int b = 0; b < 2; b++) {
        sA[b] = (uint32_t)__cvta_generic_to_shared(Abuf[b] + lrow * LDT + lcol);
        sB[b] = (uint32_t)__cvta_generic_to_shared(Bbuf[b] + lrow * LDT + lcol);
    }

    float acc[4][4][4];
    #pragma unroll
    for (int mi = 0; mi < 4; mi++)
        #pragma unroll
        for (int ni = 0; ni < 4; ni++)
            #pragma unroll
            for (int r = 0; r < 4; r++) acc[mi][ni][r] = 0.f;

    int nsteps = K / TFK;
    int V = npass * nsteps;

    // stage virtual step v into buffer buf
    auto stage = [&](int v, int buf) {
        int p  = v / nsteps;
        int ko = (v - p * nsteps) * TFK;
        const float* Ap_ = Ab[p] + ko;
        const float* Bp_ = Bb[p] + ko;
        #pragma unroll
        for (int i = 0; i < 4; i++) {
            cp16(sA[buf] + i*16, Ap_ + 4*i);
            cp16(sB[buf] + i*16, Bp_ + 4*i);
        }
        cp_commit();
    };

    stage(0, 0);

    for (int v = 0; v < V; v++) {
        int buf = v & 1;
        if (v + 1 < V) {
            stage(v + 1, buf ^ 1);
            cp_wait1();
        } else {
            cp_wait0();
        }
        __syncthreads();

        const float* As = Abuf[buf];
        const float* Bs = Bbuf[buf];
        #pragma unroll
        for (int kc = 0; kc < TFK; kc += 8) {
            uint32_t af[4][4], bf[4][2];
            #pragma unroll
            for (int mi = 0; mi < 4; mi++) {
                int R = wm * 64 + mi * 16 + g;
                af[mi][0] = __float_as_uint(As[R*LDT     + kc + c]);
                af[mi][1] = __float_as_uint(As[(R+8)*LDT + kc + c]);
                af[mi][2] = __float_as_uint(As[R*LDT     + kc + c + 4]);
                af[mi][3] = __float_as_uint(As[(R+8)*LDT + kc + c + 4]);
            }
            #pragma unroll
            for (int ni = 0; ni < 4; ni++) {
                int Nr = wn * 32 + ni * 8 + g;
                bf[ni][0] = __float_as_uint(Bs[Nr*LDT + kc + c]);
                bf[ni][1] = __float_as_uint(Bs[Nr*LDT + kc + c + 4]);
            }
            #pragma unroll
            for (int mi = 0; mi < 4; mi++)
                #pragma unroll
                for (int ni = 0; ni < 4; ni++)
                    mma_tf32(acc[mi][ni], af[mi][0], af[mi][1], af[mi][2], af[mi][3],
                             bf[ni][0], bf[ni][1]);
        }
        __syncthreads();
    }

    #pragma unroll
    for (int ni = 0; ni < 4; ni++) {
        int cc = n0 + wn * 32 + ni * 8 + 2 * c;
        float b0 = 0.f, b1 = 0.f;
        if (bias1) { b0 = bias1[cc]; b1 = bias1[cc + 1]; }
        if (bias2) { b0 += bias2[cc]; b1 += bias2[cc + 1]; }
        #pragma unroll
        for (int mi = 0; mi < 4; mi++) {
            int R = m0 + wm * 64 + mi * 16 + g;
            float2 o0 = make_float2(acc[mi][ni][0] + b0, acc[mi][ni][1] + b1);
            float2 o1 = make_float2(acc[mi][ni][2] + b0, acc[mi][ni][3] + b1);
            *(float2*)(C + (size_t)R * N + cc)       = o0;
            *(float2*)(C + (size_t)(R + 8) * N + cc) = o1;
        }
    }
}

// ---------------- software grid barrier ----------------
#define GRID_CTAS 128
__device__ __forceinline__ void grid_bar(unsigned &target) {
    __syncthreads();
    if (threadIdx.x == 0) {
        target += GRID_CTAS;
        __threadfence();
        atomicAdd(&g_bar_counter, 1u);
        while (*(volatile unsigned*)&g_bar_counter < target) { }
    }
    __syncthreads();
}

// ---------------- persistent layer kernel (fp32 recurrence, unchanged) ----------------
#define HS_PAD 36
__global__ void __launch_bounds__(256, 1)
layer_kernel(const float* __restrict__ xg, const float* __restrict__ Whh_l,
             const float* __restrict__ wq, const float* __restrict__ bq,
             const float* __restrict__ wk, const float* __restrict__ bk,
             const float* __restrict__ wv, const float* __restrict__ bv,
             const float* __restrict__ wfc, const float* __restrict__ bfc,
             const float* __restrict__ lng, const float* __restrict__ lnb,
             float* __restrict__ x_next) {
    extern __shared__ float dyn[];
    float* Wt = dyn;
    float* Hs = dyn + 256*32;

    __shared__ float hl[NB][BS];
    __shared__ float sq[NB][DK], sk[NB][DK], sv[NB][DK];
    __shared__ float attnw[NB][NB];
    __shared__ float outv[NB][DK];
    __shared__ float part[NB][2][8];
    __shared__ float mu_s[NB], rstd_s[NB];

    int cta = blockIdx.x;
    int n = cta >> 5, jt = cta & 31;
    int tid = threadIdx.x;
    int warp = tid >> 5, lane = tid & 31;

    for (int e = tid; e < 32*64; e += 256) {
        int j = e >> 6;
        int k4 = (e & 63) << 2;
        float4 w = *(const float4*)&Whh_l[(size_t)(n*1024 + jt*32 + j)*256 + k4];
        Wt[(k4+0)*32 + j] = w.x;
        Wt[(k4+1)*32 + j] = w.y;
        Wt[(k4+2)*32 + j] = w.z;
        Wt[(k4+3)*32 + j] = w.w;
    }
    __syncthreads();

    int colg = tid & 15;
    int bq4  = tid >> 4;
    int col0 = n * 1024 + jt * 32 + colg * 2;

    unsigned bar_target = 0;

    for (int t = 0; t < TT; t++) {
        ull acc2[4];
        #pragma unroll
        for (int i = 0; i < 4; i++) {
            float2 x = __ldcg((const float2*)&xg[(size_t)(t*BB + bq4*4 + i) * GATES + col0]);
            acc2[i] = *(ull*)&x;
        }
        for (int kc = 0; kc < 256; kc += 32) {
            #pragma unroll
            for (int u = 0; u < 2; u++) {
                int e = tid + u * 256;
                int b = e >> 3, k4 = (e & 7) << 2;
                float4 h = __ldcg((const float4*)&g_h[b*NHID + n*BS + kc + k4]);
                *(float4*)&Hs[b*HS_PAD + k4] = h;
            }
            __syncthreads();
            #pragma unroll
            for (int k = 0; k < 32; k += 4) {
                ull w0 = *(const ull*)&Wt[(kc+k+0)*32 + colg*2];
                ull w1 = *(const ull*)&Wt[(kc+k+1)*32 + colg*2];
                ull w2 = *(const ull*)&Wt[(kc+k+2)*32 + colg*2];
                ull w3 = *(const ull*)&Wt[(kc+k+3)*32 + colg*2];
                #pragma unroll
                for (int i = 0; i < 4; i++) {
                    float4 h = *(const float4*)&Hs[(bq4*4 + i)*HS_PAD + k];
                    ffma2(acc2[i], dup2(h.x), w0);
                    ffma2(acc2[i], dup2(h.y), w1);
                    ffma2(acc2[i], dup2(h.z), w2);
                    ffma2(acc2[i], dup2(h.w), w3);
                }
            }
            __syncthreads();
        }
        #pragma unroll
        for (int i = 0; i < 4; i++) {
            float2 v = u2f2(acc2[i]);
            __stcg((float2*)&g_gates[(size_t)(bq4*4 + i) * GATES + col0], v);
        }

        grid_bar(bar_target);

        if (cta < BB) {
            int b = cta;
            for (int e = tid; e < NB*BS; e += 256) {
                int nn = e >> 8, j = e & 255;
                const float* gr = g_gates + (size_t)b * GATES + nn * 1024 + j;
                float ig = __ldcg(gr +   0);
                float fg = __ldcg(gr + 256);
                float gg = __ldcg(gr + 512);
                float og = __ldcg(gr + 768);
                int ci = b * NHID + nn * BS + j;
                float cn = sigmoidf_(fg) * __ldcg(&g_c[ci]) + sigmoidf_(ig) * tanhf(gg);
                __stcg(&g_c[ci], cn);
                hl[nn][j] = sigmoidf_(og) * tanhf(cn);
            }
            __syncthreads();

            for (int idx = warp; idx < 3*NB*DK; idx += 8) {
                int mat = idx >> 6, nn = (idx >> 4) & 3, d = idx & 15;
                const float* W = (mat == 0 ? wq : mat == 1 ? wk : wv) + d * BS;
                float s = 0.f;
                #pragma unroll
                for (int j = lane; j < BS; j += 32) s += hl[nn][j] * W[j];
                #pragma unroll
                for (int o = 16; o; o >>= 1) s += __shfl_xor_sync(0xffffffffu, s, o);
                if (lane == 0) {
                    float bias = (mat == 0 ? bq[d] : mat == 1 ? bk[d] : bv[d]);
                    (mat == 0 ? sq : mat == 1 ? sk : sv)[nn][d] = s + bias;
                }
            }
            __syncthreads();

            if (tid < 16) {
                int nn = tid >> 2, m = tid & 3;
                float l = 0.f;
                #pragma unroll
                for (int d = 0; d < DK; d++) l += sq[nn][d] * sk[m][d];
                l *= 0.25f;
                float mx = l;
                mx = fmaxf(mx, __shfl_xor_sync(0xffffu, mx, 1));
                mx = fmaxf(mx, __shfl_xor_sync(0xffffu, mx, 2));
                float e = expf(l - mx);
                float s = e;
                s += __shfl_xor_sync(0xffffu, s, 1);
                s += __shfl_xor_sync(0xffffu, s, 2);
                attnw[nn][m] = e / s;
            }
            __syncthreads();

            if (tid < 64) {
                int nn = tid >> 4, d = tid & 15;
                float s = 0.f;
                #pragma unroll
                for (int m = 0; m < NB; m++) s += attnw[nn][m] * sv[m][d];
                outv[nn][d] = s;
            }
            __syncthreads();

            int j = tid;
            float wfr[DK];
            {
                const float4* wf4 = (const float4*)(wfc + (size_t)j * DK);
                *(float4*)(wfr)    = wf4[0];
                *(float4*)(wfr+4)  = wf4[1];
                *(float4*)(wfr+8)  = wf4[2];
                *(float4*)(wfr+12) = wf4[3];
            }
            float bfj = bfc[j], lgj = lng[j], lbj = lnb[j];
            float r[NB];
            #pragma unroll
            for (int nn = 0; nn < NB; nn++) {
                float s = bfj;
                #pragma unroll
                for (int d = 0; d < DK; d++) s += outv[nn][d] * wfr[d];
                r[nn] = s + hl[nn][j];
            }
            #pragma unroll
            for (int nn = 0; nn < NB; nn++) {
                float s1 = r[nn], s2 = r[nn] * r[nn];
                #pragma unroll
                for (int o = 16; o; o >>= 1) {
                    s1 += __shfl_xor_sync(0xffffffffu, s1, o);
                    s2 += __shfl_xor_sync(0xffffffffu, s2, o);
                }
                if (lane == 0) { part[nn][0][warp] = s1; part[nn][1][warp] = s2; }
            }
            __syncthreads();
            if (tid < 4) {
                float S1 = 0.f, S2 = 0.f;
                #pragma unroll
                for (int w = 0; w < 8; w++) { S1 += part[tid][0][w]; S2 += part[tid][1][w]; }
                float mu = S1 * (1.f / 256.f);
                mu_s[tid] = mu;
                rstd_s[tid] = rsqrtf(S2 * (1.f / 256.f) - mu * mu + 1e-5f);
            }
            __syncthreads();
            #pragma unroll
            for (int nn = 0; nn < NB; nn++) {
                float hn = (r[nn] - mu_s[nn]) * rstd_s[nn] * lgj + lbj;
                __stcg(&g_h[b * NHID + nn * BS + j], hn);
                x_next[(size_t)(t * BB + b) * NHID + nn * BS + j] = hn;
            }
        }

        grid_bar(bar_target);
    }
}

// ---------------- host orchestration ----------------
extern "C" void kernel_launch(void* const* d_in, const int* in_sizes, int n_in,
                              void* d_out, int out_size) {
    const int*   tokens = (const int*)  d_in[0];
    const float* h0     = (const float*)d_in[1];
    const float* c0     = (const float*)d_in[2];
    const float* embW   = (const float*)d_in[3];
    const float* Wih    = (const float*)d_in[4];
    const float* Whh    = (const float*)d_in[5];
    const float* bih    = (const float*)d_in[6];
    const float* bhh    = (const float*)d_in[7];
    const float* wq     = (const float*)d_in[8];
    const float* bq     = (const float*)d_in[9];
    const float* wk     = (const float*)d_in[10];
    const float* bk     = (const float*)d_in[11];
    const float* wv     = (const float*)d_in[12];
    const float* bv     = (const float*)d_in[13];
    const float* wfc    = (const float*)d_in[14];
    const float* bfc    = (const float*)d_in[15];
    const float* lng    = (const float*)d_in[16];
    const float* lnb    = (const float*)d_in[17];
    const float* decW   = (const float*)d_in[18];
    const float* decb   = (const float*)d_in[19];
    float* out = (float*)d_out;

    float *x0, *x1, *xg, *decWt, *Whi, *Wlo, *xhi, *xlo;
    cudaGetSymbolAddress((void**)&x0, g_x0);
    cudaGetSymbolAddress((void**)&x1, g_x1);
    cudaGetSymbolAddress((void**)&xg, g_xg);
    cudaGetSymbolAddress((void**)&decWt, g_decW_t);
    cudaGetSymbolAddress((void**)&Whi, g_Wih_hi);
    cudaGetSymbolAddress((void**)&Wlo, g_Wih_lo);
    cudaGetSymbolAddress((void**)&xhi, g_x_hi);
    cudaGetSymbolAddress((void**)&xlo, g_x_lo);

    const int gemm_smem = 4 * TILE_F * sizeof(float);            // 73728 B
    cudaFuncSetAttribute(gemm_tf32, cudaFuncAttributeMaxDynamicSharedMemorySize, gemm_smem);
    const int layer_smem = (256*32 + 64*HS_PAD) * sizeof(float); // 41984 B

    // precision prep
    cvt_tf32_kernel<<<(NTOK*NHID)/1024, 256>>>(decW, decWt);
    split_tf32_kernel<<<(NLAYERS*GATES*NINP)/1024, 256>>>(Wih, Whi, Wlo);

    embed_kernel<<<ROWS, 256>>>(tokens, embW);

    float* xcur = x0;
    float* xnext = x1;
    for (int l = 0; l < NLAYERS; l++) {
        init_state_kernel<<<64, 256>>>(h0 + (size_t)l * BB * NHID,
                                       c0 + (size_t)l * BB * NHID);
        // 3xTF32: xg = x_hi@W_hi + x_lo@W_hi + x_hi@W_lo + biases (near-fp32 precision)
        split_tf32_kernel<<<(ROWS*NHID)/1024, 256>>>(xcur, xhi, xlo);
        const float* Whi_l = Whi + (size_t)l * GATES * NINP;
        const float* Wlo_l = Wlo + (size_t)l * GATES * NINP;
        gemm_tf32<<<dim3(GATES/128, ROWS/128), 256, gemm_smem>>>(
            xhi, xlo, xhi, Whi_l, Whi_l, Wlo_l, 3,
            bih + (size_t)l * GATES, bhh + (size_t)l * GATES,
            xg, ROWS, GATES, NINP);
        layer_kernel<<<GRID_CTAS, 256, layer_smem>>>(
            xg, Whh + (size_t)l * NB * 1024 * 256,
            wq, bq, wk, bk, wv, bv, wfc, bfc, lng, lnb, xnext);
        save_state_kernel<<<64, 256>>>(out + H_OFF + (size_t)l * BB * NHID,
                                       out + C_OFF + (size_t)l * BB * NHID);
        float* tmp = xcur; xcur = xnext; xnext = tmp;
    }

    // decode: single-pass tf32 (direct output, no recurrent amplification)
    cvt_tf32_kernel<<<(ROWS*NHID)/1024, 256>>>(xcur, xhi);
    gemm_tf32<<<dim3(NTOK/128, ROWS/128), 256, gemm_smem>>>(
        xhi, xhi, xhi, decWt, decWt, decWt, 1,
        decb, nullptr, out, ROWS, NTOK, NINP);
}

// round 9
// speedup vs baseline: 1.3751x; 1.0019x over previous
#include <cuda_runtime.h>
#include <cstdint>
#include <cstddef>

// ---------------- problem constants ----------------
#define NLAYERS 2
#define NB      4
#define BS      256
#define NHID    1024
#define NINP    1024
#define NTOK    32000
#define TT      64
#define BB      64
#define DK      16
#define ROWS    (TT*BB)          // 4096
#define GATES   (NB*4*BS)        // 4096

#define H_OFF   ((size_t)ROWS*NTOK)
#define C_OFF   (H_OFF + (size_t)NLAYERS*BB*NHID)

// ---------------- device scratch ----------------
__device__ float g_x0[(size_t)ROWS*NHID];
__device__ float g_x1[(size_t)ROWS*NHID];
__device__ float g_xg[(size_t)ROWS*GATES];
__device__ float g_gates[(size_t)BB*GATES];
__device__ float g_h[BB*NHID];
__device__ float g_c[BB*NHID];
__device__ unsigned g_bar_counter;
// tf32 copies
__device__ float g_decW_t[(size_t)NTOK*NHID];            // 131 MB (tf32-rounded)
__device__ float g_Wih_hi[(size_t)NLAYERS*GATES*NINP];   // 33.5 MB
__device__ float g_Wih_lo[(size_t)NLAYERS*GATES*NINP];   // 33.5 MB
__device__ float g_x_hi[(size_t)ROWS*NHID];              // 16.8 MB
__device__ float g_x_lo[(size_t)ROWS*NHID];              // 16.8 MB

__device__ __forceinline__ float sigmoidf_(float x) { return 1.f / (1.f + expf(-x)); }

typedef unsigned long long ull;

__device__ __forceinline__ void ffma2(ull &d, ull a, ull b) {
    asm("fma.rn.f32x2 %0, %1, %2, %3;" : "=l"(d) : "l"(a), "l"(b), "l"(d));
}
__device__ __forceinline__ ull dup2(float x) {
    ull r; unsigned u = __float_as_uint(x);
    asm("mov.b64 %0, {%1, %1};" : "=l"(r) : "r"(u));
    return r;
}
__device__ __forceinline__ float2 u2f2(ull v) {
    float2 f; unsigned lo, hi;
    asm("mov.b64 {%0, %1}, %2;" : "=r"(lo), "=r"(hi) : "l"(v));
    f.x = __uint_as_float(lo); f.y = __uint_as_float(hi);
    return f;
}

__device__ __forceinline__ float f2tf_f(float f) {
    uint32_t r; asm("cvt.rna.tf32.f32 %0, %1;" : "=r"(r) : "f"(f));
    return __uint_as_float(r);
}
__device__ __forceinline__ void cp16(uint32_t saddr, const void* g) {
    asm volatile("cp.async.cg.shared.global [%0], [%1], 16;" :: "r"(saddr), "l"(g));
}
__device__ __forceinline__ void cp_commit() { asm volatile("cp.async.commit_group;"); }
__device__ __forceinline__ void cp_wait1()  { asm volatile("cp.async.wait_group 1;"); }
__device__ __forceinline__ void cp_wait0()  { asm volatile("cp.async.wait_group 0;"); }

__device__ __forceinline__ void mma_tf32(float c[4],
                                         uint32_t a0, uint32_t a1, uint32_t a2, uint32_t a3,
                                         uint32_t b0, uint32_t b1) {
    asm("mma.sync.aligned.m16n8k8.row.col.f32.tf32.tf32.f32 "
        "{%0,%1,%2,%3}, {%4,%5,%6,%7}, {%8,%9}, {%0,%1,%2,%3};"
        : "+f"(c[0]), "+f"(c[1]), "+f"(c[2]), "+f"(c[3])
        : "r"(a0), "r"(a1), "r"(a2), "r"(a3), "r"(b0), "r"(b1));
}

// ---------------- tf32 conversion: out = round_tf32(in) ----------------
__global__ void cvt_tf32_kernel(const float* __restrict__ in, float* __restrict__ out) {
    size_t i = ((size_t)blockIdx.x * 256 + threadIdx.x) * 4;
    float4 v = *(const float4*)(in + i);
    float4 o;
    o.x = f2tf_f(v.x); o.y = f2tf_f(v.y); o.z = f2tf_f(v.z); o.w = f2tf_f(v.w);
    *(float4*)(out + i) = o;
}

// ---------------- tf32 split: hi = round_tf32(in), lo = round_tf32(in - hi) ----------------
__global__ void split_tf32_kernel(const float* __restrict__ in,
                                  float* __restrict__ hi, float* __restrict__ lo) {
    size_t i = ((size_t)blockIdx.x * 256 + threadIdx.x) * 4;
    float4 v = *(const float4*)(in + i);
    float4 h, l;
    h.x = f2tf_f(v.x); l.x = f2tf_f(v.x - h.x);
    h.y = f2tf_f(v.y); l.y = f2tf_f(v.y - h.y);
    h.z = f2tf_f(v.z); l.z = f2tf_f(v.z - h.z);
    h.w = f2tf_f(v.w); l.w = f2tf_f(v.w - h.w);
    *(float4*)(hi + i) = h;
    *(float4*)(lo + i) = l;
}

// ---------------- embedding gather ----------------
__global__ void embed_kernel(const int* __restrict__ tokens,
                             const float* __restrict__ embW) {
    int row = blockIdx.x;
    int tok = tokens[row];
    const float4* src = (const float4*)(embW + (size_t)tok * NINP);
    float4* dst = (float4*)(g_x0 + (size_t)row * NINP);
    dst[threadIdx.x] = src[threadIdx.x];
}

// ---------------- state init / save ----------------
__global__ void init_state_kernel(const float* __restrict__ h0l,
                                  const float* __restrict__ c0l) {
    int i = blockIdx.x * blockDim.x + threadIdx.x;
    ((float4*)g_h)[i] = ((const float4*)h0l)[i];
    ((float4*)g_c)[i] = ((const float4*)c0l)[i];
    if (i == 0) g_bar_counter = 0;
}

__global__ void save_state_kernel(float* __restrict__ outh, float* __restrict__ outc) {
    int i = blockIdx.x * blockDim.x + threadIdx.x;
    ((float4*)outh)[i] = ((const float4*)g_h)[i];
    ((float4*)outc)[i] = ((const float4*)g_c)[i];
}

// ---------------- tf32 tensor-core GEMM with multi-pass accumulation ----------------
// C[M,N] = sum_p A_p[M,K] @ B_p[N,K]^T + bias1 + bias2   (npass = 1 or 3)
// 128x128 tile, BK=32, cp.async double buffer, 8 warps (wm=warp&1 64 rows, wn=warp>>1 32 cols).
#define TFK 32
#define LDT 36
#define TILE_F (128*LDT)
__global__ void __launch_bounds__(256, 2)
gemm_tf32(const float* __restrict__ A0, const float* __restrict__ A1, const float* __restrict__ A2,
          const float* __restrict__ B0, const float* __restrict__ B1, const float* __restrict__ B2,
          int npass,
          const float* __restrict__ bias1, const float* __restrict__ bias2,
          float* __restrict__ C, int M, int N, int K) {
    extern __shared__ float sm[];
    float* Abuf[2] = { sm,            sm + TILE_F };
    float* Bbuf[2] = { sm + 2*TILE_F, sm + 3*TILE_F };

    int tid  = threadIdx.x;
    int m0 = blockIdx.y * 128, n0 = blockIdx.x * 128;
    int warp = tid >> 5, lane = tid & 31;
    int wm = warp & 1, wn = warp >> 1;
    int g = lane >> 2, c = lane & 3;

    int lrow = tid >> 1, lcol = (tid & 1) * 16;
    size_t aoff = (size_t)(m0 + lrow) * K + lcol;
    size_t boff = (size_t)(n0 + lrow) * K + lcol;
    const float* Ab[3] = { A0 + aoff, A1 + aoff, A2 + aoff };
    const float* Bb[3] = { B0 + boff, B1 + boff, B2 + boff };

    uint32_t sA[2], sB[2];
    #pragma unroll
    for (int b = 0; b < 2; b++) {
        sA[b] = (uint32_t)__cvta_generic_to_shared(Abuf[b] + lrow * LDT + lcol);
        sB[b] = (uint32_t)__cvta_generic_to_shared(Bbuf[b] + lrow * LDT + lcol);
    }

    float acc[4][4][4];
    #pragma unroll
    for (int mi = 0; mi < 4; mi++)
        #pragma unroll
        for (int ni = 0; ni < 4; ni++)
            #pragma unroll
            for (int r = 0; r < 4; r++) acc[mi][ni][r] = 0.f;

    int nsteps = K / TFK;
    int V = npass * nsteps;

    // stage virtual step v into buffer buf
    auto stage = [&](int v, int buf) {
        int p  = v / nsteps;
        int ko = (v - p * nsteps) * TFK;
        const float* Ap_ = Ab[p] + ko;
        const float* Bp_ = Bb[p] + ko;
        #pragma unroll
        for (int i = 0; i < 4; i++) {
            cp16(sA[buf] + i*16, Ap_ + 4*i);
            cp16(sB[buf] + i*16, Bp_ + 4*i);
        }
        cp_commit();
    };

    stage(0, 0);

    for (int v = 0; v < V; v++) {
        int buf = v & 1;
        if (v + 1 < V) {
            stage(v + 1, buf ^ 1);
            cp_wait1();
        } else {
            cp_wait0();
        }
        __syncthreads();

        const float* As = Abuf[buf];
        const float* Bs = Bbuf[buf];
        #pragma unroll
        for (int kc = 0; kc < TFK; kc += 8) {
            uint32_t af[4][4], bf[4][2];
            #pragma unroll
            for (int mi = 0; mi < 4; mi++) {
                int R = wm * 64 + mi * 16 + g;
                af[mi][0] = __float_as_uint(As[R*LDT     + kc + c]);
                af[mi][1] = __float_as_uint(As[(R+8)*LDT + kc + c]);
                af[mi][2] = __float_as_uint(As[R*LDT     + kc + c + 4]);
                af[mi][3] = __float_as_uint(As[(R+8)*LDT + kc + c + 4]);
            }
            #pragma unroll
            for (int ni = 0; ni < 4; ni++) {
                int Nr = wn * 32 + ni * 8 + g;
                bf[ni][0] = __float_as_uint(Bs[Nr*LDT + kc + c]);
                bf[ni][1] = __float_as_uint(Bs[Nr*LDT + kc + c + 4]);
            }
            #pragma unroll
            for (int mi = 0; mi < 4; mi++)
                #pragma unroll
                for (int ni = 0; ni < 4; ni++)
                    mma_tf32(acc[mi][ni], af[mi][0], af[mi][1], af[mi][2], af[mi][3],
                             bf[ni][0], bf[ni][1]);
        }
        __syncthreads();
    }

    #pragma unroll
    for (int ni = 0; ni < 4; ni++) {
        int cc = n0 + wn * 32 + ni * 8 + 2 * c;
        float b0 = 0.f, b1 = 0.f;
        if (bias1) { b0 = bias1[cc]; b1 = bias1[cc + 1]; }
        if (bias2) { b0 += bias2[cc]; b1 += bias2[cc + 1]; }
        #pragma unroll
        for (int mi = 0; mi < 4; mi++) {
            int R = m0 + wm * 64 + mi * 16 + g;
            float2 o0 = make_float2(acc[mi][ni][0] + b0, acc[mi][ni][1] + b1);
            float2 o1 = make_float2(acc[mi][ni][2] + b0, acc[mi][ni][3] + b1);
            *(float2*)(C + (size_t)R * N + cc)       = o0;
            *(float2*)(C + (size_t)(R + 8) * N + cc) = o1;
        }
    }
}

// ---------------- software grid barrier ----------------
#define GRID_CTAS 128
__device__ __forceinline__ void grid_bar(unsigned &target) {
    __syncthreads();
    if (threadIdx.x == 0) {
        target += GRID_CTAS;
        __threadfence();
        atomicAdd(&g_bar_counter, 1u);
        while (*(volatile unsigned*)&g_bar_counter < target) { }
    }
    __syncthreads();
}

// ---------------- persistent layer kernel (fp32 recurrence, unchanged) ----------------
#define HS_PAD 36
__global__ void __launch_bounds__(256, 1)
layer_kernel(const float* __restrict__ xg, const float* __restrict__ Whh_l,
             const float* __restrict__ wq, const float* __restrict__ bq,
             const float* __restrict__ wk, const float* __restrict__ bk,
             const float* __restrict__ wv, const float* __restrict__ bv,
             const float* __restrict__ wfc, const float* __restrict__ bfc,
             const float* __restrict__ lng, const float* __restrict__ lnb,
             float* __restrict__ x_next) {
    extern __shared__ float dyn[];
    float* Wt = dyn;
    float* Hs = dyn + 256*32;

    __shared__ float hl[NB][BS];
    __shared__ float sq[NB][DK], sk[NB][DK], sv[NB][DK];
    __shared__ float attnw[NB][NB];
    __shared__ float outv[NB][DK];
    __shared__ float part[NB][2][8];
    __shared__ float mu_s[NB], rstd_s[NB];

    int cta = blockIdx.x;
    int n = cta >> 5, jt = cta & 31;
    int tid = threadIdx.x;
    int warp = tid >> 5, lane = tid & 31;

    for (int e = tid; e < 32*64; e += 256) {
        int j = e >> 6;
        int k4 = (e & 63) << 2;
        float4 w = *(const float4*)&Whh_l[(size_t)(n*1024 + jt*32 + j)*256 + k4];
        Wt[(k4+0)*32 + j] = w.x;
        Wt[(k4+1)*32 + j] = w.y;
        Wt[(k4+2)*32 + j] = w.z;
        Wt[(k4+3)*32 + j] = w.w;
    }
    __syncthreads();

    int colg = tid & 15;
    int bq4  = tid >> 4;
    int col0 = n * 1024 + jt * 32 + colg * 2;

    unsigned bar_target = 0;

    for (int t = 0; t < TT; t++) {
        ull acc2[4];
        #pragma unroll
        for (int i = 0; i < 4; i++) {
            float2 x = __ldcg((const float2*)&xg[(size_t)(t*BB + bq4*4 + i) * GATES + col0]);
            acc2[i] = *(ull*)&x;
        }
        for (int kc = 0; kc < 256; kc += 32) {
            #pragma unroll
            for (int u = 0; u < 2; u++) {
                int e = tid + u * 256;
                int b = e >> 3, k4 = (e & 7) << 2;
                float4 h = __ldcg((const float4*)&g_h[b*NHID + n*BS + kc + k4]);
                *(float4*)&Hs[b*HS_PAD + k4] = h;
            }
            __syncthreads();
            #pragma unroll
            for (int k = 0; k < 32; k += 4) {
                ull w0 = *(const ull*)&Wt[(kc+k+0)*32 + colg*2];
                ull w1 = *(const ull*)&Wt[(kc+k+1)*32 + colg*2];
                ull w2 = *(const ull*)&Wt[(kc+k+2)*32 + colg*2];
                ull w3 = *(const ull*)&Wt[(kc+k+3)*32 + colg*2];
                #pragma unroll
                for (int i = 0; i < 4; i++) {
                    float4 h = *(const float4*)&Hs[(bq4*4 + i)*HS_PAD + k];
                    ffma2(acc2[i], dup2(h.x), w0);
                    ffma2(acc2[i], dup2(h.y), w1);
                    ffma2(acc2[i], dup2(h.z), w2);
                    ffma2(acc2[i], dup2(h.w), w3);
                }
            }
            __syncthreads();
        }
        #pragma unroll
        for (int i = 0; i < 4; i++) {
            float2 v = u2f2(acc2[i]);
            __stcg((float2*)&g_gates[(size_t)(bq4*4 + i) * GATES + col0], v);
        }

        grid_bar(bar_target);

        if (cta < BB) {
            int b = cta;
            for (int e = tid; e < NB*BS; e += 256) {
                int nn = e >> 8, j = e & 255;
                const float* gr = g_gates + (size_t)b * GATES + nn * 1024 + j;
                float ig = __ldcg(gr +   0);
                float fg = __ldcg(gr + 256);
                float gg = __ldcg(gr + 512);
                float og = __ldcg(gr + 768);
                int ci = b * NHID + nn * BS + j;
                float cn = sigmoidf_(fg) * __ldcg(&g_c[ci]) + sigmoidf_(ig) * tanhf(gg);
                __stcg(&g_c[ci], cn);
                hl[nn][j] = sigmoidf_(og) * tanhf(cn);
            }
            __syncthreads();

            for (int idx = warp; idx < 3*NB*DK; idx += 8) {
                int mat = idx >> 6, nn = (idx >> 4) & 3, d = idx & 15;
                const float* W = (mat == 0 ? wq : mat == 1 ? wk : wv) + d * BS;
                float s = 0.f;
                #pragma unroll
                for (int j = lane; j < BS; j += 32) s += hl[nn][j] * W[j];
                #pragma unroll
                for (int o = 16; o; o >>= 1) s += __shfl_xor_sync(0xffffffffu, s, o);
                if (lane == 0) {
                    float bias = (mat == 0 ? bq[d] : mat == 1 ? bk[d] : bv[d]);
                    (mat == 0 ? sq : mat == 1 ? sk : sv)[nn][d] = s + bias;
                }
            }
            __syncthreads();

            if (tid < 16) {
                int nn = tid >> 2, m = tid & 3;
                float l = 0.f;
                #pragma unroll
                for (int d = 0; d < DK; d++) l += sq[nn][d] * sk[m][d];
                l *= 0.25f;
                float mx = l;
                mx = fmaxf(mx, __shfl_xor_sync(0xffffu, mx, 1));
                mx = fmaxf(mx, __shfl_xor_sync(0xffffu, mx, 2));
                float e = expf(l - mx);
                float s = e;
                s += __shfl_xor_sync(0xffffu, s, 1);
                s += __shfl_xor_sync(0xffffu, s, 2);
                attnw[nn][m] = e / s;
            }
            __syncthreads();

            if (tid < 64) {
                int nn = tid >> 4, d = tid & 15;
                float s = 0.f;
                #pragma unroll
                for (int m = 0; m < NB; m++) s += attnw[nn][m] * sv[m][d];
                outv[nn][d] = s;
            }
            __syncthreads();

            int j = tid;
            float wfr[DK];
            {
                const float4* wf4 = (const float4*)(wfc + (size_t)j * DK);
                *(float4*)(wfr)    = wf4[0];
                *(float4*)(wfr+4)  = wf4[1];
                *(float4*)(wfr+8)  = wf4[2];
                *(float4*)(wfr+12) = wf4[3];
            }
            float bfj = bfc[j], lgj = lng[j], lbj = lnb[j];
            float r[NB];
            #pragma unroll
            for (int nn = 0; nn < NB; nn++) {
                float s = bfj;
                #pragma unroll
                for (int d = 0; d < DK; d++) s += outv[nn][d] * wfr[d];
                r[nn] = s + hl[nn][j];
            }
            #pragma unroll
            for (int nn = 0; nn < NB; nn++) {
                float s1 = r[nn], s2 = r[nn] * r[nn];
                #pragma unroll
                for (int o = 16; o; o >>= 1) {
                    s1 += __shfl_xor_sync(0xffffffffu, s1, o);
                    s2 += __shfl_xor_sync(0xffffffffu, s2, o);
                }
                if (lane == 0) { part[nn][0][warp] = s1; part[nn][1][warp] = s2; }
            }
            __syncthreads();
            if (tid < 4) {
                float S1 = 0.f, S2 = 0.f;
                #pragma unroll
                for (int w = 0; w < 8; w++) { S1 += part[tid][0][w]; S2 += part[tid][1][w]; }
                float mu = S1 * (1.f / 256.f);
                mu_s[tid] = mu;
                rstd_s[tid] = rsqrtf(S2 * (1.f / 256.f) - mu * mu + 1e-5f);
            }
            __syncthreads();
            #pragma unroll
            for (int nn = 0; nn < NB; nn++) {
                float hn = (r[nn] - mu_s[nn]) * rstd_s[nn] * lgj + lbj;
                __stcg(&g_h[b * NHID + nn * BS + j], hn);
                x_next[(size_t)(t * BB + b) * NHID + nn * BS + j] = hn;
            }
        }

        grid_bar(bar_target);
    }
}

// ---------------- host orchestration ----------------
extern "C" void kernel_launch(void* const* d_in, const int* in_sizes, int n_in,
                              void* d_out, int out_size) {
    const int*   tokens = (const int*)  d_in[0];
    const float* h0     = (const float*)d_in[1];
    const float* c0     = (const float*)d_in[2];
    const float* embW   = (const float*)d_in[3];
    const float* Wih    = (const float*)d_in[4];
    const float* Whh    = (const float*)d_in[5];
    const float* bih    = (const float*)d_in[6];
    const float* bhh    = (const float*)d_in[7];
    const float* wq     = (const float*)d_in[8];
    const float* bq     = (const float*)d_in[9];
    const float* wk     = (const float*)d_in[10];
    const float* bk     = (const float*)d_in[11];
    const float* wv     = (const float*)d_in[12];
    const float* bv     = (const float*)d_in[13];
    const float* wfc    = (const float*)d_in[14];
    const float* bfc    = (const float*)d_in[15];
    const float* lng    = (const float*)d_in[16];
    const float* lnb    = (const float*)d_in[17];
    const float* decW   = (const float*)d_in[18];
    const float* decb   = (const float*)d_in[19];
    float* out = (float*)d_out;

    float *x0, *x1, *xg, *decWt, *Whi, *Wlo, *xhi, *xlo;
    cudaGetSymbolAddress((void**)&x0, g_x0);
    cudaGetSymbolAddress((void**)&x1, g_x1);
    cudaGetSymbolAddress((void**)&xg, g_xg);
    cudaGetSymbolAddress((void**)&decWt, g_decW_t);
    cudaGetSymbolAddress((void**)&Whi, g_Wih_hi);
    cudaGetSymbolAddress((void**)&Wlo, g_Wih_lo);
    cudaGetSymbolAddress((void**)&xhi, g_x_hi);
    cudaGetSymbolAddress((void**)&xlo, g_x_lo);

    const int gemm_smem = 4 * TILE_F * sizeof(float);            // 73728 B
    cudaFuncSetAttribute(gemm_tf32, cudaFuncAttributeMaxDynamicSharedMemorySize, gemm_smem);
    const int layer_smem = (256*32 + 64*HS_PAD) * sizeof(float); // 41984 B

    // precision prep
    cvt_tf32_kernel<<<(NTOK*NHID)/1024, 256>>>(decW, decWt);
    split_tf32_kernel<<<(NLAYERS*GATES*NINP)/1024, 256>>>(Wih, Whi, Wlo);

    embed_kernel<<<ROWS, 256>>>(tokens, embW);

    float* xcur = x0;
    float* xnext = x1;
    for (int l = 0; l < NLAYERS; l++) {
        init_state_kernel<<<64, 256>>>(h0 + (size_t)l * BB * NHID,
                                       c0 + (size_t)l * BB * NHID);
        // 3xTF32: xg = x_hi@W_hi + x_lo@W_hi + x_hi@W_lo + biases (near-fp32 precision)
        split_tf32_kernel<<<(ROWS*NHID)/1024, 256>>>(xcur, xhi, xlo);
        const float* Whi_l = Whi + (size_t)l * GATES * NINP;
        const float* Wlo_l = Wlo + (size_t)l * GATES * NINP;
        gemm_tf32<<<dim3(GATES/128, ROWS/128), 256, gemm_smem>>>(
            xhi, xlo, xhi, Whi_l, Whi_l, Wlo_l, 3,
            bih + (size_t)l * GATES, bhh + (size_t)l * GATES,
            xg, ROWS, GATES, NINP);
        layer_kernel<<<GRID_CTAS, 256, layer_smem>>>(
            xg, Whh + (size_t)l * NB * 1024 * 256,
            wq, bq, wk, bk, wv, bv, wfc, bfc, lng, lnb, xnext);
        save_state_kernel<<<64, 256>>>(out + H_OFF + (size_t)l * BB * NHID,
                                       out + C_OFF + (size_t)l * BB * NHID);
        float* tmp = xcur; xcur = xnext; xnext = tmp;
    }

    // decode: single-pass tf32 (direct output, no recurrent amplification)
    cvt_tf32_kernel<<<(ROWS*NHID)/1024, 256>>>(xcur, xhi);
    gemm_tf32<<<dim3(NTOK/128, ROWS/128), 256, gemm_smem>>>(
        xhi, xhi, xhi, decWt, decWt, decWt, 1,
        decb, nullptr, out, ROWS, NTOK, NINP);
}